// round 6
// baseline (speedup 1.0000x reference)
#include <cuda_runtime.h>

// out[b] = 0.5 * mean(sigmoid(conv2d_valid(data, w4x4) + b)) for all b (broadcast).
// Quantum term is exactly 0: theta in {0, pi}; RX(pi) = -i*X and the CX chain are
// basis permutations / global phases on the uniform H^n|0> state => qexp[b] = 0.

#define IMG 64
#define OUT 61
#define NPOS (OUT * OUT)          // 3721
#define NBATCH 256
#define THREADS 512
#define CHUNK 8                   // x-positions per thread
#define NTASKS (OUT * CHUNK)      // 61 rows * 8 chunks = 488

__device__ float        g_sum   = 0.0f;
__device__ unsigned int g_count = 0u;

__global__ __launch_bounds__(THREADS)
void conv_sigmoid_mean_kernel(const float* __restrict__ data,
                              const float* __restrict__ w,
                              const float* __restrict__ b,
                              float* __restrict__ out) {
    // pad by one float4: chunk 7 reads float4 index (y+3)*16 + 16 (garbage, masked)
    __shared__ float img[IMG * IMG + 4];
    __shared__ float sw[16];
    __shared__ float warp_sums[THREADS / 32];
    __shared__ int   is_last;
    __shared__ float total;

    const int n   = blockIdx.x;
    const int tid = threadIdx.x;

    // Load image: 1024 float4, 2 per thread
    const float4* src4 = reinterpret_cast<const float4*>(data + (size_t)n * IMG * IMG);
    float4* img4 = reinterpret_cast<float4*>(img);
    #pragma unroll
    for (int i = tid; i < IMG * IMG / 4; i += THREADS) {
        img4[i] = src4[i];
    }
    if (tid < 16) sw[tid] = w[tid];
    __syncthreads();

    float lsum = 0.0f;

    if (tid < NTASKS) {
        const int y     = tid >> 3;          // 0..60
        const int chunk = tid & 7;           // 0..7
        const int x0    = chunk * CHUNK;     // 0,8,...,56 (float4-aligned)
        const float bias = b[0];

        float acc[CHUNK];
        #pragma unroll
        for (int p = 0; p < CHUNK; p++) acc[p] = bias;

        #pragma unroll
        for (int i = 0; i < 4; i++) {
            // 12-value window for this input row: 3 x LDS.128
            const float4* r = img4 + (y + i) * (IMG / 4) + (x0 >> 2);
            float4 v0 = r[0], v1 = r[1], v2 = r[2];
            float win[12] = {v0.x, v0.y, v0.z, v0.w,
                             v1.x, v1.y, v1.z, v1.w,
                             v2.x, v2.y, v2.z, v2.w};
            #pragma unroll
            for (int j = 0; j < 4; j++) {
                const float wij = sw[i * 4 + j];
                #pragma unroll
                for (int p = 0; p < CHUNK; p++) {
                    acc[p] = fmaf(win[p + j], wij, acc[p]);
                }
            }
        }

        #pragma unroll
        for (int p = 0; p < CHUNK; p++) {
            if (x0 + p < OUT) {                       // mask tail of last chunk
                lsum += 1.0f / (1.0f + __expf(-acc[p]));
            }
        }
    }

    // warp reduce
    #pragma unroll
    for (int off = 16; off > 0; off >>= 1)
        lsum += __shfl_xor_sync(0xFFFFFFFFu, lsum, off);

    const int wid = tid >> 5;
    const int lid = tid & 31;
    if (lid == 0) warp_sums[wid] = lsum;
    __syncthreads();

    if (tid == 0) {
        float s = 0.0f;
        #pragma unroll
        for (int i = 0; i < THREADS / 32; i++) s += warp_sums[i];
        atomicAdd(&g_sum, s);
        __threadfence();
        unsigned int prev = atomicAdd(&g_count, 1u);
        is_last = (prev == (unsigned)(gridDim.x - 1)) ? 1 : 0;
        if (is_last) {
            total = atomicAdd(&g_sum, 0.0f);   // all prior adds visible (fence-before-count)
        }
    }
    __syncthreads();

    if (is_last && tid < NBATCH) {
        const float scale = 0.5f / (float)(NBATCH * NPOS);
        out[tid] = total * scale;
        if (tid == 0) {                        // self-clean for next graph replay
            g_sum   = 0.0f;
            g_count = 0u;
            __threadfence();
        }
    }
}

extern "C" void kernel_launch(void* const* d_in, const int* in_sizes, int n_in,
                              void* d_out, int out_size) {
    const float* data = (const float*)d_in[0];   // 256*1*64*64
    const float* w    = (const float*)d_in[1];   // 1*1*4*4
    const float* b    = (const float*)d_in[2];   // 1
    float* out = (float*)d_out;                  // 256 floats

    conv_sigmoid_mean_kernel<<<NBATCH, THREADS>>>(data, w, b, out);
}